// round 3
// baseline (speedup 1.0000x reference)
#include <cuda_runtime.h>
#include <cuda_bf16.h>

// RepformerLayer: nf=1, nloc=1024, nnei=128, ng2=32, nd=32, nh=4
// One CTA per location i (1024 CTAs, 256 threads).
// R2: packed fma.rn.f32x2 (FFMA2) on all GEMM phases; fused Q+K projection pass.
//
// Algebra:
//   g2_out = b_head + sum_h A_h @ P_h,  P_h = g2 @ W2_h,  W2_h = w_v_h @ w_head_h (precomputed)
//   h2_out = (sum_h w_eq[h] * A_h) @ h2

#define NLOC 1024
#define NNEI 128
#define NG2  32
#define NH   4

#define INV_SQRT_ND 0.17677669529663687f   // 1/sqrt(32)
#define INV_SQRT3   0.57735026918962576f   // 1/sqrt(3)
#define ATTNW_SHIFT 20.0f

typedef unsigned long long u64;

__device__ __forceinline__ u64 pk2(float lo, float hi) {
    u64 r;
    asm("mov.b64 %0, {%1, %2};" : "=l"(r) : "f"(lo), "f"(hi));
    return r;
}
__device__ __forceinline__ void upk2(u64 v, float& lo, float& hi) {
    asm("mov.b64 {%0, %1}, %2;" : "=f"(lo), "=f"(hi) : "l"(v));
}
__device__ __forceinline__ void fma2(u64& d, u64 a, u64 b) {
    asm("fma.rn.f32x2 %0, %1, %2, %0;" : "+l"(d) : "l"(a), "l"(b));
}
__device__ __forceinline__ float hsum2(u64 v) {
    float lo, hi; upk2(v, lo, hi); return lo + hi;
}

// Precomputed W2[h][j][o] = sum_g w_v[j, g*4+h] * w_head[g*4+h, o]
__device__ float g_W2[NH][NG2][NG2];

__global__ void precompute_W2_kernel(const float* __restrict__ w_v,
                                     const float* __restrict__ w_head) {
    int t = blockIdx.x * blockDim.x + threadIdx.x;
    if (t >= NH * NG2 * NG2) return;
    int o = t & 31;
    int j = (t >> 5) & 31;
    int h = t >> 10;
    float s = 0.0f;
#pragma unroll
    for (int g = 0; g < 32; g++)
        s = fmaf(w_v[j * 128 + g * 4 + h], w_head[(g * 4 + h) * 32 + o], s);
    g_W2[h][j][o] = s;
}

// ---- shared memory layout (floats) ----
// G2   [128][32]   : 0      .. 4096
// QS   [128][36]   : 4096   .. 8704     (pad 36: conflict-free .128)
// KS   [128][36]   : 8704   .. 13312
// PS   [128][32]   : 13312  .. 17408
// AS   [128][128]  : 17408  .. 33792    (broadcast reads / lane-consecutive writes: no pad)
// ASUM [128][132]  : 33792  .. 50688    (pad 132: conflict-free epilogue .128 per-thread-row)
// H2S  [128][4]    : 50688  .. 51200
// SWS  [128]       : 51200  .. 51328
// MFS  [128]       : 51328  .. 51456
#define SM_FLOATS 51456

__global__ __launch_bounds__(256, 1)
void repformer_kernel(const float* __restrict__ g2,
                      const float* __restrict__ h2,
                      const float* __restrict__ sw,
                      const float* __restrict__ w_qk,
                      const float* __restrict__ b_head,
                      const float* __restrict__ w_eqhead,
                      const int*   __restrict__ nlist_mask,
                      float* __restrict__ out) {
    extern __shared__ float sm[];
    float* G2   = sm;
    float* QS   = sm + 4096;
    float* KS   = sm + 8704;
    float* PS   = sm + 13312;
    float* AS   = sm + 17408;
    float* ASUM = sm + 33792;
    float* H2S  = sm + 50688;
    float* SWS  = sm + 51200;
    float* MFS  = sm + 51328;

    const int i    = blockIdx.x;
    const int tid  = threadIdx.x;
    const int lane = tid & 31;
    const int w    = tid >> 5;   // warp 0..7

    // ---- load tile ----
    {
        const float4* src = (const float4*)(g2 + (size_t)i * NNEI * NG2);
        float4* dst = (float4*)G2;
        for (int v = tid; v < NNEI * NG2 / 4; v += 256) dst[v] = src[v];
        for (int n = tid; n < NNEI; n += 256) {
            size_t base = ((size_t)i * NNEI + n);
            H2S[n * 4 + 0] = h2[base * 3 + 0];
            H2S[n * 4 + 1] = h2[base * 3 + 1];
            H2S[n * 4 + 2] = h2[base * 3 + 2];
            H2S[n * 4 + 3] = 0.0f;
            SWS[n] = sw[base];
            MFS[n] = nlist_mask[base] ? 1.0f : 0.0f;
        }
    }
    __syncthreads();

    // phase-c packed accumulator: warp w owns rows w*16..w*16+15, lane owns column `lane`
    // acc holds {even-k partial, odd-k partial}
    u64 outAcc[16];
#pragma unroll
    for (int r = 0; r < 16; r++) outAcc[r] = 0ull;

#pragma unroll 1
    for (int h = 0; h < NH; h++) {
        const float weq = w_eqhead[h];

        // ============ phase a1: fused Q,K projection ============
        // thread: column = lane, rows = w + 8*r (r=0..15)
        {
            u64 wq[16], wk[16];
#pragma unroll
            for (int t = 0; t < 16; t++) {
                wq[t] = pk2(__ldg(&w_qk[(2 * t) * 256 + lane * 8 + h]),
                            __ldg(&w_qk[(2 * t + 1) * 256 + lane * 8 + h]));
                wk[t] = pk2(__ldg(&w_qk[(2 * t) * 256 + lane * 8 + 4 + h]),
                            __ldg(&w_qk[(2 * t + 1) * 256 + lane * 8 + 4 + h]));
            }
            u64 aq[16], ak[16];
#pragma unroll
            for (int r = 0; r < 16; r++) { aq[r] = 0ull; ak[r] = 0ull; }
#pragma unroll
            for (int j4 = 0; j4 < 8; j4++) {
#pragma unroll
                for (int r = 0; r < 16; r++) {
                    ulonglong2 g = *(const ulonglong2*)(G2 + (w + 8 * r) * 32 + j4 * 4);
                    fma2(aq[r], g.x, wq[2 * j4]);
                    fma2(aq[r], g.y, wq[2 * j4 + 1]);
                    fma2(ak[r], g.x, wk[2 * j4]);
                    fma2(ak[r], g.y, wk[2 * j4 + 1]);
                }
            }
#pragma unroll
            for (int r = 0; r < 16; r++) {
                QS[(w + 8 * r) * 36 + lane] = hsum2(aq[r]) * INV_SQRT_ND;
                KS[(w + 8 * r) * 36 + lane] = hsum2(ak[r]);
            }
        }
        // ============ phase a2: PS = g2 @ W2_h ============
        {
            u64 wp[16];
#pragma unroll
            for (int t = 0; t < 16; t++)
                wp[t] = pk2(g_W2[h][2 * t][lane], g_W2[h][2 * t + 1][lane]);
            u64 ap[16];
#pragma unroll
            for (int r = 0; r < 16; r++) ap[r] = 0ull;
#pragma unroll
            for (int j4 = 0; j4 < 8; j4++) {
#pragma unroll
                for (int r = 0; r < 16; r++) {
                    ulonglong2 g = *(const ulonglong2*)(G2 + (w + 8 * r) * 32 + j4 * 4);
                    fma2(ap[r], g.x, wp[2 * j4]);
                    fma2(ap[r], g.y, wp[2 * j4 + 1]);
                }
            }
#pragma unroll
            for (int r = 0; r < 16; r++)
                PS[(w + 8 * r) * 32 + lane] = hsum2(ap[r]);
        }
        __syncthreads();

        // ============ phase b: QK^T + scaling + softmax + masking ============
        // warp w owns rows w*16..w*16+15 in 2 groups of 8; lane owns k = lane + 32*m
#pragma unroll 1
        for (int grp = 0; grp < 2; grp++) {
            const int qbase = w * 16 + grp * 8;

            float hk0[4], hk1[4], hk2[4], swk[4], kc[4];
#pragma unroll
            for (int m = 0; m < 4; m++) {
                int k = lane + 32 * m;
                hk0[m] = H2S[k * 4 + 0];
                hk1[m] = H2S[k * 4 + 1];
                hk2[m] = H2S[k * 4 + 2];
                swk[m] = SWS[k];
                kc[m]  = swk[m] * MFS[k];
            }

            u64 acc[8][4];
#pragma unroll
            for (int r = 0; r < 8; r++)
#pragma unroll
                for (int m = 0; m < 4; m++) acc[r][m] = 0ull;

#pragma unroll
            for (int d4 = 0; d4 < 8; d4++) {
                ulonglong2 kvv[4];
#pragma unroll
                for (int m = 0; m < 4; m++)
                    kvv[m] = *(const ulonglong2*)(KS + (lane + 32 * m) * 36 + d4 * 4);
#pragma unroll
                for (int r = 0; r < 8; r++) {
                    ulonglong2 qv = *(const ulonglong2*)(QS + (qbase + r) * 36 + d4 * 4);
#pragma unroll
                    for (int m = 0; m < 4; m++) {
                        fma2(acc[r][m], qv.x, kvv[m].x);
                        fma2(acc[r][m], qv.y, kvv[m].y);
                    }
                }
            }

#pragma unroll
            for (int r = 0; r < 8; r++) {
                const int q = qbase + r;
                const float hq0 = H2S[q * 4 + 0];
                const float hq1 = H2S[q * 4 + 1];
                const float hq2 = H2S[q * 4 + 2];
                const float swq = SWS[q];
                const float mq  = MFS[q];

                float hh[4], val[4];
#pragma unroll
                for (int m = 0; m < 4; m++) {
                    hh[m] = fmaf(hq0, hk0[m], fmaf(hq1, hk1[m], hq2 * hk2[m]));
                    float a = hsum2(acc[r][m]) * hh[m];
                    val[m] = (a + ATTNW_SHIFT) * swq * swk[m] - ATTNW_SHIFT;
                }
                float mx = fmaxf(fmaxf(val[0], val[1]), fmaxf(val[2], val[3]));
#pragma unroll
                for (int s = 16; s > 0; s >>= 1)
                    mx = fmaxf(mx, __shfl_xor_sync(0xffffffffu, mx, s));
                float ssum = 0.0f;
#pragma unroll
                for (int m = 0; m < 4; m++) {
                    val[m] = __expf(val[m] - mx);
                    ssum += val[m];
                }
#pragma unroll
                for (int s = 16; s > 0; s >>= 1)
                    ssum += __shfl_xor_sync(0xffffffffu, ssum, s);
                // rowc folds: 1/sum, swq, mask_q, 1/sqrt(3)
                const float rowc = __frcp_rn(ssum) * swq * mq * INV_SQRT3;
#pragma unroll
                for (int m = 0; m < 4; m++) {
                    float A = val[m] * rowc * kc[m] * hh[m];
                    int k = lane + 32 * m;
                    AS[q * 128 + k] = A;
                    if (h == 0) ASUM[q * 132 + k] = weq * A;
                    else        ASUM[q * 132 + k] += weq * A;
                }
            }
        }
        __syncthreads();

        // ============ phase c: outAcc[r] += sum_k AS[row][k] * PS[k][lane] ============
        {
            const int rowbase = w * 16;
#pragma unroll 4
            for (int k4 = 0; k4 < 32; k4++) {
                float p0 = PS[(k4 * 4 + 0) * 32 + lane];
                float p1 = PS[(k4 * 4 + 1) * 32 + lane];
                float p2 = PS[(k4 * 4 + 2) * 32 + lane];
                float p3 = PS[(k4 * 4 + 3) * 32 + lane];
                u64 pA = pk2(p0, p1);
                u64 pB = pk2(p2, p3);
#pragma unroll
                for (int r = 0; r < 16; r++) {
                    ulonglong2 a = *(const ulonglong2*)(AS + (rowbase + r) * 128 + k4 * 4);
                    fma2(outAcc[r], a.x, pA);
                    fma2(outAcc[r], a.y, pB);
                }
            }
        }
        __syncthreads();   // before next head overwrites QS/KS/PS/AS
    }

    // ---- epilogue: g2_out ----
    {
        const float b = b_head[lane];
        const int rowbase = w * 16;
#pragma unroll
        for (int r = 0; r < 16; r++) {
            int q = rowbase + r;
            out[((size_t)i * NNEI + q) * 32 + lane] = hsum2(outAcc[r]) + b;
        }
    }

    // ---- epilogue: h2_out = ASUM @ h2 ----
    if (tid < 128) {
        const int q = tid;
        float s0 = 0.0f, s1 = 0.0f, s2 = 0.0f;
#pragma unroll 4
        for (int k4 = 0; k4 < 32; k4++) {
            float4 a = *(const float4*)(ASUM + q * 132 + k4 * 4);
            float av[4] = {a.x, a.y, a.z, a.w};
#pragma unroll
            for (int u = 0; u < 4; u++) {
                int k = k4 * 4 + u;
                s0 = fmaf(av[u], H2S[k * 4 + 0], s0);
                s1 = fmaf(av[u], H2S[k * 4 + 1], s1);
                s2 = fmaf(av[u], H2S[k * 4 + 2], s2);
            }
        }
        float* oh = out + (size_t)NLOC * NNEI * 32;
        size_t base = ((size_t)i * NNEI + q) * 3;
        oh[base + 0] = s0;
        oh[base + 1] = s1;
        oh[base + 2] = s2;
    }
}

extern "C" void kernel_launch(void* const* d_in, const int* in_sizes, int n_in,
                              void* d_out, int out_size) {
    const float* g2       = (const float*)d_in[0];
    const float* h2       = (const float*)d_in[1];
    const float* sw       = (const float*)d_in[2];
    const float* w_qk     = (const float*)d_in[3];
    const float* w_v      = (const float*)d_in[4];
    const float* w_head   = (const float*)d_in[5];
    const float* b_head   = (const float*)d_in[6];
    const float* w_eqhead = (const float*)d_in[7];
    const int*   nmask    = (const int*)d_in[8];
    float* out = (float*)d_out;

    precompute_W2_kernel<<<16, 256>>>(w_v, w_head);

    const size_t smem = (size_t)SM_FLOATS * sizeof(float);   // ~201 KB
    cudaFuncSetAttribute(repformer_kernel,
                         cudaFuncAttributeMaxDynamicSharedMemorySize, (int)smem);
    repformer_kernel<<<NLOC, 256, smem>>>(g2, h2, sw, w_qk, b_head, w_eqhead, nmask, out);
}

// round 4
// speedup vs baseline: 1.3958x; 1.3958x over previous
#include <cuda_runtime.h>
#include <cuda_bf16.h>

// RepformerLayer: nf=1, nloc=1024, nnei=128, ng2=32, nd=32, nh=4
// One CTA per location i (1024 CTAs, 512 threads = 16 warps, 8 rows/warp).
// R3: wide CTA for occupancy (4 warps/SMSP); FFMA2 only in low-pressure phases (a, c).
//
// Algebra:
//   g2_out = b_head + sum_h A_h @ P_h,  P_h = g2 @ W2_h,  W2_h = w_v_h @ w_head_h (precomputed)
//   h2_out = (sum_h w_eq[h] * A_h) @ h2

#define NLOC 1024
#define NNEI 128
#define NG2  32
#define NH   4

#define INV_SQRT_ND 0.17677669529663687f   // 1/sqrt(32)
#define INV_SQRT3   0.57735026918962576f   // 1/sqrt(3)
#define ATTNW_SHIFT 20.0f

typedef unsigned long long u64;

__device__ __forceinline__ u64 pk2(float lo, float hi) {
    u64 r;
    asm("mov.b64 %0, {%1, %2};" : "=l"(r) : "f"(lo), "f"(hi));
    return r;
}
__device__ __forceinline__ void upk2(u64 v, float& lo, float& hi) {
    asm("mov.b64 {%0, %1}, %2;" : "=f"(lo), "=f"(hi) : "l"(v));
}
__device__ __forceinline__ void fma2(u64& d, u64 a, u64 b) {
    asm("fma.rn.f32x2 %0, %1, %2, %0;" : "+l"(d) : "l"(a), "l"(b));
}
__device__ __forceinline__ float hsum2(u64 v) {
    float lo, hi; upk2(v, lo, hi); return lo + hi;
}

// Precomputed W2[h][j][o] = sum_g w_v[j, g*4+h] * w_head[g*4+h, o]
__device__ float g_W2[NH][NG2][NG2];

__global__ void precompute_W2_kernel(const float* __restrict__ w_v,
                                     const float* __restrict__ w_head) {
    int t = blockIdx.x * blockDim.x + threadIdx.x;
    if (t >= NH * NG2 * NG2) return;
    int o = t & 31;
    int j = (t >> 5) & 31;
    int h = t >> 10;
    float s = 0.0f;
#pragma unroll
    for (int g = 0; g < 32; g++)
        s = fmaf(w_v[j * 128 + g * 4 + h], w_head[(g * 4 + h) * 32 + o], s);
    g_W2[h][j][o] = s;
}

// ---- shared memory layout (floats) ----
// G2   [128][32]   : 0      .. 4096
// QS   [128][36]   : 4096   .. 8704     (pad 36: conflict-free .128)
// KS   [128][36]   : 8704   .. 13312
// PS   [128][32]   : 13312  .. 17408
// AS   [128][128]  : 17408  .. 33792
// ASUM [128][132]  : 33792  .. 50688    (pad 132: conflict-free epilogue .128)
// H2S  [128][4]    : 50688  .. 51200
// SWS  [128]       : 51200  .. 51328
// MFS  [128]       : 51328  .. 51456
#define SM_FLOATS 51456

__global__ __launch_bounds__(512, 1)
void repformer_kernel(const float* __restrict__ g2,
                      const float* __restrict__ h2,
                      const float* __restrict__ sw,
                      const float* __restrict__ w_qk,
                      const float* __restrict__ b_head,
                      const float* __restrict__ w_eqhead,
                      const int*   __restrict__ nlist_mask,
                      float* __restrict__ out) {
    extern __shared__ float sm[];
    float* G2   = sm;
    float* QS   = sm + 4096;
    float* KS   = sm + 8704;
    float* PS   = sm + 13312;
    float* AS   = sm + 17408;
    float* ASUM = sm + 33792;
    float* H2S  = sm + 50688;
    float* SWS  = sm + 51200;
    float* MFS  = sm + 51328;

    const int i    = blockIdx.x;
    const int tid  = threadIdx.x;
    const int lane = tid & 31;
    const int w    = tid >> 5;   // warp 0..15

    // ---- load tile ----
    {
        const float4* src = (const float4*)(g2 + (size_t)i * NNEI * NG2);
        float4* dst = (float4*)G2;
        for (int v = tid; v < NNEI * NG2 / 4; v += 512) dst[v] = src[v];
        if (tid < NNEI) {
            int n = tid;
            size_t base = ((size_t)i * NNEI + n);
            H2S[n * 4 + 0] = h2[base * 3 + 0];
            H2S[n * 4 + 1] = h2[base * 3 + 1];
            H2S[n * 4 + 2] = h2[base * 3 + 2];
            H2S[n * 4 + 3] = 0.0f;
            SWS[n] = sw[base];
            MFS[n] = nlist_mask[base] ? 1.0f : 0.0f;
        }
    }
    __syncthreads();

    // phase-c accumulator: warp w owns rows w*8..w*8+7, lane owns column `lane`
    u64 outAcc[8];
#pragma unroll
    for (int r = 0; r < 8; r++) outAcc[r] = 0ull;

#pragma unroll 1
    for (int h = 0; h < NH; h++) {
        const float weq = w_eqhead[h];

        // ============ phase a: QS = g2@Wq/sqrt(nd), KS = g2@Wk, PS = g2@W2_h ============
        // thread: column = lane, rows = w + 16*r (r=0..7). Packed weights + FFMA2.
#pragma unroll 1
        for (int m = 0; m < 3; m++) {
            u64 wreg[16];
            if (m == 0) {
#pragma unroll
                for (int t = 0; t < 16; t++)
                    wreg[t] = pk2(__ldg(&w_qk[(2 * t) * 256 + lane * 8 + h]),
                                  __ldg(&w_qk[(2 * t + 1) * 256 + lane * 8 + h]));
            } else if (m == 1) {
#pragma unroll
                for (int t = 0; t < 16; t++)
                    wreg[t] = pk2(__ldg(&w_qk[(2 * t) * 256 + lane * 8 + 4 + h]),
                                  __ldg(&w_qk[(2 * t + 1) * 256 + lane * 8 + 4 + h]));
            } else {
#pragma unroll
                for (int t = 0; t < 16; t++)
                    wreg[t] = pk2(g_W2[h][2 * t][lane], g_W2[h][2 * t + 1][lane]);
            }
            u64 acc[8];
#pragma unroll
            for (int r = 0; r < 8; r++) acc[r] = 0ull;
#pragma unroll
            for (int j4 = 0; j4 < 8; j4++) {
#pragma unroll
                for (int r = 0; r < 8; r++) {
                    ulonglong2 g = *(const ulonglong2*)(G2 + (w + 16 * r) * 32 + j4 * 4);
                    fma2(acc[r], g.x, wreg[2 * j4]);
                    fma2(acc[r], g.y, wreg[2 * j4 + 1]);
                }
            }
            if (m == 0) {
#pragma unroll
                for (int r = 0; r < 8; r++)
                    QS[(w + 16 * r) * 36 + lane] = hsum2(acc[r]) * INV_SQRT_ND;
            } else if (m == 1) {
#pragma unroll
                for (int r = 0; r < 8; r++)
                    KS[(w + 16 * r) * 36 + lane] = hsum2(acc[r]);
            } else {
#pragma unroll
                for (int r = 0; r < 8; r++)
                    PS[(w + 16 * r) * 32 + lane] = hsum2(acc[r]);
            }
        }
        __syncthreads();

        // ============ phase b: QK^T + scaling + softmax + masking (scalar) ============
        // warp w owns rows w*8..w*8+7; lane owns k = lane + 32*m
        {
            const int qbase = w * 8;

            float hk0[4], hk1[4], hk2[4], swk[4], kc[4];
#pragma unroll
            for (int m = 0; m < 4; m++) {
                int k = lane + 32 * m;
                hk0[m] = H2S[k * 4 + 0];
                hk1[m] = H2S[k * 4 + 1];
                hk2[m] = H2S[k * 4 + 2];
                swk[m] = SWS[k];
                kc[m]  = swk[m] * MFS[k];
            }

            float acc[8][4];
#pragma unroll
            for (int r = 0; r < 8; r++)
#pragma unroll
                for (int m = 0; m < 4; m++) acc[r][m] = 0.0f;

#pragma unroll
            for (int d4 = 0; d4 < 8; d4++) {
                float4 kvv[4];
#pragma unroll
                for (int m = 0; m < 4; m++)
                    kvv[m] = *(const float4*)(KS + (lane + 32 * m) * 36 + d4 * 4);
#pragma unroll
                for (int r = 0; r < 8; r++) {
                    float4 qv = *(const float4*)(QS + (qbase + r) * 36 + d4 * 4);
#pragma unroll
                    for (int m = 0; m < 4; m++) {
                        acc[r][m] = fmaf(qv.x, kvv[m].x, acc[r][m]);
                        acc[r][m] = fmaf(qv.y, kvv[m].y, acc[r][m]);
                        acc[r][m] = fmaf(qv.z, kvv[m].z, acc[r][m]);
                        acc[r][m] = fmaf(qv.w, kvv[m].w, acc[r][m]);
                    }
                }
            }

#pragma unroll
            for (int r = 0; r < 8; r++) {
                const int q = qbase + r;
                const float hq0 = H2S[q * 4 + 0];
                const float hq1 = H2S[q * 4 + 1];
                const float hq2 = H2S[q * 4 + 2];
                const float swq = SWS[q];
                const float mq  = MFS[q];

                float hh[4], val[4];
#pragma unroll
                for (int m = 0; m < 4; m++) {
                    hh[m] = fmaf(hq0, hk0[m], fmaf(hq1, hk1[m], hq2 * hk2[m]));
                    float a = acc[r][m] * hh[m];
                    val[m] = (a + ATTNW_SHIFT) * swq * swk[m] - ATTNW_SHIFT;
                }
                float mx = fmaxf(fmaxf(val[0], val[1]), fmaxf(val[2], val[3]));
#pragma unroll
                for (int s = 16; s > 0; s >>= 1)
                    mx = fmaxf(mx, __shfl_xor_sync(0xffffffffu, mx, s));
                float ssum = 0.0f;
#pragma unroll
                for (int m = 0; m < 4; m++) {
                    val[m] = __expf(val[m] - mx);
                    ssum += val[m];
                }
#pragma unroll
                for (int s = 16; s > 0; s >>= 1)
                    ssum += __shfl_xor_sync(0xffffffffu, ssum, s);
                const float rowc = __frcp_rn(ssum) * swq * mq * INV_SQRT3;
#pragma unroll
                for (int m = 0; m < 4; m++) {
                    float A = val[m] * rowc * kc[m] * hh[m];
                    int k = lane + 32 * m;
                    AS[q * 128 + k] = A;
                    if (h == 0) ASUM[q * 132 + k] = weq * A;
                    else        ASUM[q * 132 + k] += weq * A;
                }
            }
        }
        __syncthreads();

        // ============ phase c: outAcc[r] += sum_k AS[row][k] * PS[k][lane] (FFMA2) ============
        {
            const int rowbase = w * 8;
#pragma unroll 4
            for (int k4 = 0; k4 < 32; k4++) {
                float p0 = PS[(k4 * 4 + 0) * 32 + lane];
                float p1 = PS[(k4 * 4 + 1) * 32 + lane];
                float p2 = PS[(k4 * 4 + 2) * 32 + lane];
                float p3 = PS[(k4 * 4 + 3) * 32 + lane];
                u64 pA = pk2(p0, p1);
                u64 pB = pk2(p2, p3);
#pragma unroll
                for (int r = 0; r < 8; r++) {
                    ulonglong2 a = *(const ulonglong2*)(AS + (rowbase + r) * 128 + k4 * 4);
                    fma2(outAcc[r], a.x, pA);
                    fma2(outAcc[r], a.y, pB);
                }
            }
        }
        __syncthreads();   // before next head overwrites QS/KS/PS/AS
    }

    // ---- epilogue: g2_out ----
    {
        const float b = b_head[lane];
        const int rowbase = w * 8;
#pragma unroll
        for (int r = 0; r < 8; r++) {
            int q = rowbase + r;
            out[((size_t)i * NNEI + q) * 32 + lane] = hsum2(outAcc[r]) + b;
        }
    }

    // ---- epilogue: h2_out = ASUM @ h2 ----
    if (tid < 128) {
        const int q = tid;
        float s0 = 0.0f, s1 = 0.0f, s2 = 0.0f;
#pragma unroll 4
        for (int k4 = 0; k4 < 32; k4++) {
            float4 a = *(const float4*)(ASUM + q * 132 + k4 * 4);
            float av[4] = {a.x, a.y, a.z, a.w};
#pragma unroll
            for (int u = 0; u < 4; u++) {
                int k = k4 * 4 + u;
                s0 = fmaf(av[u], H2S[k * 4 + 0], s0);
                s1 = fmaf(av[u], H2S[k * 4 + 1], s1);
                s2 = fmaf(av[u], H2S[k * 4 + 2], s2);
            }
        }
        float* oh = out + (size_t)NLOC * NNEI * 32;
        size_t base = ((size_t)i * NNEI + q) * 3;
        oh[base + 0] = s0;
        oh[base + 1] = s1;
        oh[base + 2] = s2;
    }
}

extern "C" void kernel_launch(void* const* d_in, const int* in_sizes, int n_in,
                              void* d_out, int out_size) {
    const float* g2       = (const float*)d_in[0];
    const float* h2       = (const float*)d_in[1];
    const float* sw       = (const float*)d_in[2];
    const float* w_qk     = (const float*)d_in[3];
    const float* w_v      = (const float*)d_in[4];
    const float* w_head   = (const float*)d_in[5];
    const float* b_head   = (const float*)d_in[6];
    const float* w_eqhead = (const float*)d_in[7];
    const int*   nmask    = (const int*)d_in[8];
    float* out = (float*)d_out;

    precompute_W2_kernel<<<16, 256>>>(w_v, w_head);

    const size_t smem = (size_t)SM_FLOATS * sizeof(float);   // ~201 KB
    cudaFuncSetAttribute(repformer_kernel,
                         cudaFuncAttributeMaxDynamicSharedMemorySize, (int)smem);
    repformer_kernel<<<NLOC, 512, smem>>>(g2, h2, sw, w_qk, b_head, w_eqhead, nmask, out);
}